// round 14
// baseline (speedup 1.0000x reference)
#include <cuda_runtime.h>
#include <math.h>

// Problem constants
#define T_LEN 32768
#define D_IN  512
#define H_DIM 1024
#define S_DIM 256
#define G3    (3 * H_DIM)   // 3072

// Scan configuration: 128 persistent CTAs, 8 h-outputs per CTA, 24 w_hh rows per CTA.
#define NC           128
#define JPC          (H_DIM / NC)        // 8
#define SCAN_THREADS 256                 // 8 warps, 3 rows per warp

typedef unsigned long long u64;

// -------- Scratch (device globals; no dynamic allocation allowed) ----------
__device__ float g_igates[(size_t)T_LEN * G3];   // ~403 MB
__device__ float g_hs[(size_t)T_LEN * H_DIM];    // ~134 MB
__device__ float g_h[2][H_DIM];                  // ping-pong hidden state
__device__ unsigned g_flags[NC * 8];             // per-CTA step flags, 32B stride

// ---------------------------------------------------------------------------
// Init: h = tanh(h0); reset flags (runs every replay).
// ---------------------------------------------------------------------------
__global__ void init_kernel(const float* __restrict__ h0)
{
    int i = threadIdx.x;
    if (i < H_DIM) g_h[0][i] = tanhf(h0[i]);
    if (i < NC)    g_flags[i * 8] = 0u;
}

// ---------------------------------------------------------------------------
// Tiled fp32 GEMM:  C[m][n] = sum_k A[m][k] * B[n][k] + bias[n]
//   A row-major [M,K], B row-major [N,K] ("NT" layout, both K-contiguous).
//   mode 0: A = param (y),  C = g_igates                        (igates GEMM)
//   mode 1: A = g_hs,       C = d_out split + softplus epilogue (output GEMM)
// Tiles: 128x128x16, 256 threads. Warp tile 32x64; conflict-free float4
// fragment reads (lane stride 4 words; A broadcast per phase, B spans banks).
// ---------------------------------------------------------------------------
__global__ __launch_bounds__(256) void gemm_kernel(
    const float* __restrict__ Ain,
    const float* __restrict__ Bm,
    const float* __restrict__ bias,
    float* __restrict__ Cout,
    int M, int N, int K, int mode)
{
    __shared__ float As[16][128];
    __shared__ float Bs[16][128];

    const float* A = (mode == 0) ? Ain : g_hs;

    int bm = blockIdx.y;
    int bn = blockIdx.x;
    int tid  = threadIdx.x;
    int warp = tid >> 5;
    int lane = tid & 31;
    int wy = warp >> 1;          // 0..3  -> warp row (32 rows each)
    int wx = warp & 1;           // 0..1  -> warp col (64 cols each)
    int r  = lane >> 3;          // 0..3
    int c  = lane & 7;           // 0..7

    const float* Ab = A  + (size_t)bm * 128 * K;
    const float* Bb = Bm + (size_t)bn * 128 * K;

    float acc[2][4][2][4];
#pragma unroll
    for (int ia = 0; ia < 2; ia++)
#pragma unroll
        for (int i = 0; i < 4; i++)
#pragma unroll
            for (int jb = 0; jb < 2; jb++)
#pragma unroll
                for (int j = 0; j < 4; j++) acc[ia][i][jb][j] = 0.f;

    for (int kt = 0; kt < K; kt += 16) {
#pragma unroll
        for (int s = 0; s < 2; s++) {
            int idx = tid * 2 + s;          // 0..511
            int row = idx >> 2;             // 0..127
            int k4  = idx & 3;              // 0..3
            float4 va = *(const float4*)(Ab + (size_t)row * K + kt + k4 * 4);
            As[k4 * 4 + 0][row] = va.x;
            As[k4 * 4 + 1][row] = va.y;
            As[k4 * 4 + 2][row] = va.z;
            As[k4 * 4 + 3][row] = va.w;
            float4 vb = *(const float4*)(Bb + (size_t)row * K + kt + k4 * 4);
            Bs[k4 * 4 + 0][row] = vb.x;
            Bs[k4 * 4 + 1][row] = vb.y;
            Bs[k4 * 4 + 2][row] = vb.z;
            Bs[k4 * 4 + 3][row] = vb.w;
        }
        __syncthreads();

#pragma unroll
        for (int kk = 0; kk < 16; kk++) {
            float4 a0 = *(const float4*)&As[kk][wy * 32 + r * 4];
            float4 a1 = *(const float4*)&As[kk][wy * 32 + r * 4 + 16];
            float4 b0 = *(const float4*)&Bs[kk][wx * 64 + c * 4];
            float4 b1 = *(const float4*)&Bs[kk][wx * 64 + c * 4 + 32];
            float av[2][4] = {{a0.x, a0.y, a0.z, a0.w}, {a1.x, a1.y, a1.z, a1.w}};
            float bv[2][4] = {{b0.x, b0.y, b0.z, b0.w}, {b1.x, b1.y, b1.z, b1.w}};
#pragma unroll
            for (int ia = 0; ia < 2; ia++)
#pragma unroll
                for (int i = 0; i < 4; i++)
#pragma unroll
                    for (int jb = 0; jb < 2; jb++)
#pragma unroll
                        for (int j = 0; j < 4; j++)
                            acc[ia][i][jb][j] += av[ia][i] * bv[jb][j];
        }
        __syncthreads();
    }

#pragma unroll
    for (int ia = 0; ia < 2; ia++) {
#pragma unroll
        for (int i = 0; i < 4; i++) {
            int m = bm * 128 + wy * 32 + r * 4 + ia * 16 + i;
#pragma unroll
            for (int jb = 0; jb < 2; jb++) {
#pragma unroll
                for (int j = 0; j < 4; j++) {
                    int n = bn * 128 + wx * 64 + c * 4 + jb * 32 + j;
                    float v = acc[ia][i][jb][j] + bias[n];
                    if (mode == 0) {
                        g_igates[(size_t)m * G3 + n] = v;
                    } else {
                        if (n < S_DIM) {
                            Cout[(size_t)m * S_DIM + n] = v;             // nat1
                        } else {
                            // softplus, stable: max(x,0)+log1p(exp(-|x|))
                            float sp = fmaxf(v, 0.f) + log1pf(expf(-fabsf(v)));
                            Cout[(size_t)T_LEN * S_DIM + (size_t)m * S_DIM + (n - S_DIM)] = sp;
                        }
                    }
                }
            }
        }
    }
}

// ---------------------------------------------------------------------------
// Persistent GRU scan.
//   128 CTAs x 256 threads. CTA c owns h-indices [8c, 8c+8).
//   24 w_hh rows per CTA in registers, held as f32x2 pairs (ulonglong2).
//   Per step:
//     1. prefetch ig (overlaps spin)
//     2. distributed flag wait: 4 warps, each lane acquires ONE distinct
//        32B-padded flag (no atomics, no shared-address contention)
//     3. stage h (4KB) into smem once, coalesced ld.cg
//     4. matvec with fma.rn.f32x2 (2x fp32 FMA rate), shfl reduce
//     5. gate math on 8 units; st.cg h'; st.release.gpu own flag
// ---------------------------------------------------------------------------
__global__ __launch_bounds__(SCAN_THREADS, 1) void scan_kernel(
    const float* __restrict__ w_hh,
    const float* __restrict__ bn_vec)
{
    int c    = blockIdx.x;
    int tid  = threadIdx.x;
    int warp = tid >> 5;
    int lane = tid & 31;

    // --- Load this CTA's weight slice into registers as f32x2 pairs -----
    // lr = warp*3+rr in 0..23; global row = (lr>>3)*H + c*8 + (lr&7).
    ulonglong2 w[3][8];
#pragma unroll
    for (int rr = 0; rr < 3; rr++) {
        int lr   = warp * 3 + rr;
        int grow = (lr >> 3) * H_DIM + c * JPC + (lr & 7);
        const float* wr = w_hh + (size_t)grow * H_DIM;
#pragma unroll
        for (int i = 0; i < 8; i++)
            w[rr][i] = *(const ulonglong2*)(wr + i * 128 + lane * 4);
    }

    float bnv = (tid < JPC) ? bn_vec[c * JPC + tid] : 0.f;

    __shared__ float4 hsm4[H_DIM / 4];   // staged h, 4KB
    __shared__ float  red[24];
    __shared__ float  igs[24];

    const unsigned* my_poll = (warp < 4) ? &g_flags[(warp * 32 + lane) * 8] : 0;
    unsigned* my_flag = &g_flags[c * 8];

    for (int t = 0; t < T_LEN; t++) {
        const float4* hb4 = (const float4*)g_h[t & 1];

        // 1) Prefetch input gates (independent of the barrier; overlaps spin).
        float ig = 0.f;
        if (tid < 24) {
            int gate = tid >> 3, joff = tid & 7;
            ig = __ldcg(&g_igates[(size_t)t * G3 + gate * H_DIM + c * JPC + joff]);
        }

        // 2) Distributed flag wait: need every flag >= t.
        //    ld.acquire.gpu orders the subsequent h loads after the observed
        //    flag value (pairs with the producer's st.release.gpu).
        if (warp < 4) {
            unsigned v;
            do {
                asm volatile("ld.global.acquire.gpu.u32 %0, [%1];"
                             : "=r"(v) : "l"(my_poll));
            } while (v < (unsigned)t);
        }
        __syncthreads();

        // 3) Stage full h (4KB) into smem: one coalesced float4/thread, .cg
        //    (bypasses stale L1; L1 is not coherent across SMs).
        hsm4[tid] = __ldcg(hb4 + tid);
        __syncthreads();

        float hprev = (tid < JPC) ? ((const float*)hsm4)[c * JPC + tid] : 0.f;

        // 4) 3 dot-products of length 1024 per warp via packed f32x2 FMA.
        u64 a0l = 0, a0h = 0, a1l = 0, a1h = 0, a2l = 0, a2h = 0;
#pragma unroll
        for (int i = 0; i < 8; i++) {
            ulonglong2 h2 = *(const ulonglong2*)&hsm4[i * 32 + lane];
            asm volatile("fma.rn.f32x2 %0, %1, %2, %0;" : "+l"(a0l) : "l"(w[0][i].x), "l"(h2.x));
            asm volatile("fma.rn.f32x2 %0, %1, %2, %0;" : "+l"(a0h) : "l"(w[0][i].y), "l"(h2.y));
            asm volatile("fma.rn.f32x2 %0, %1, %2, %0;" : "+l"(a1l) : "l"(w[1][i].x), "l"(h2.x));
            asm volatile("fma.rn.f32x2 %0, %1, %2, %0;" : "+l"(a1h) : "l"(w[1][i].y), "l"(h2.y));
            asm volatile("fma.rn.f32x2 %0, %1, %2, %0;" : "+l"(a2l) : "l"(w[2][i].x), "l"(h2.x));
            asm volatile("fma.rn.f32x2 %0, %1, %2, %0;" : "+l"(a2h) : "l"(w[2][i].y), "l"(h2.y));
        }
        // Unpack f32x2 accumulators and finish per-lane sums.
        float acc0 = __uint_as_float((unsigned)a0l) + __uint_as_float((unsigned)(a0l >> 32))
                   + __uint_as_float((unsigned)a0h) + __uint_as_float((unsigned)(a0h >> 32));
        float acc1 = __uint_as_float((unsigned)a1l) + __uint_as_float((unsigned)(a1l >> 32))
                   + __uint_as_float((unsigned)a1h) + __uint_as_float((unsigned)(a1h >> 32));
        float acc2 = __uint_as_float((unsigned)a2l) + __uint_as_float((unsigned)(a2l >> 32))
                   + __uint_as_float((unsigned)a2h) + __uint_as_float((unsigned)(a2h >> 32));
#pragma unroll
        for (int off = 16; off > 0; off >>= 1) {
            acc0 += __shfl_xor_sync(0xffffffffu, acc0, off);
            acc1 += __shfl_xor_sync(0xffffffffu, acc1, off);
            acc2 += __shfl_xor_sync(0xffffffffu, acc2, off);
        }
        if (lane == 0) {
            red[warp * 3 + 0] = acc0;
            red[warp * 3 + 1] = acc1;
            red[warp * 3 + 2] = acc2;
        }
        if (tid < 24) igs[tid] = ig;
        __syncthreads();

        // 5) Gate math for this CTA's 8 hidden units; publish h'.
        float hnew = 0.f;
        if (tid < JPC) {
            float hrv = red[tid], hzv = red[8 + tid], hnv = red[16 + tid];
            float irv = igs[tid], izv = igs[8 + tid], innv = igs[16 + tid];
            float r = 1.f / (1.f + expf(-(irv + hrv)));
            float z = 1.f / (1.f + expf(-(izv + hzv)));
            float n = tanhf(innv + r * (hnv + bnv));
            hnew = n + z * (hprev - n);
            // st.cg: write goes to L2 (the coherence point) directly.
            asm volatile("st.global.cg.f32 [%0], %1;"
                         :: "l"(&g_h[(t + 1) & 1][c * JPC + tid]), "f"(hnew));
        }
        __syncthreads();   // all 8 h' stores issued before the flag release

        if (tid == 0) {
            // release store: orders this CTA's h' writes before the flag.
            asm volatile("st.global.release.gpu.u32 [%0], %1;"
                         :: "l"(my_flag), "r"((unsigned)(t + 1)));
        }

        // g_hs store off the critical path (after flag publication).
        if (tid < JPC)
            g_hs[(size_t)t * H_DIM + c * JPC + tid] = hnew;
    }
}

// ---------------------------------------------------------------------------
extern "C" void kernel_launch(void* const* d_in, const int* in_sizes, int n_in,
                              void* d_out, int out_size)
{
    const float* y     = (const float*)d_in[0];  // [T, D]
    const float* h0    = (const float*)d_in[1];  // [H]
    const float* w_ih  = (const float*)d_in[2];  // [3H, D]
    const float* w_hh  = (const float*)d_in[3];  // [3H, H]
    const float* b     = (const float*)d_in[4];  // [3H]
    const float* bn    = (const float*)d_in[5];  // [H]
    const float* w_out = (const float*)d_in[6];  // [2S, H]
    const float* b_out = (const float*)d_in[7];  // [2S]
    float* out = (float*)d_out;                  // [T*S nat1][T*S softplus(nat2)]

    // 1) init h + flags
    init_kernel<<<1, 1024>>>(h0);

    // 2) igates = y @ w_ih.T + b   -> g_igates  [T, 3H]
    {
        dim3 grid(G3 / 128, T_LEN / 128);
        gemm_kernel<<<grid, 256>>>(y, w_ih, b, nullptr, T_LEN, G3, D_IN, 0);
    }

    // 3) sequential GRU scan -> g_hs [T, H]
    scan_kernel<<<NC, SCAN_THREADS>>>(w_hh, bn);

    // 4) out = hs @ w_out.T + b_out; split + softplus -> d_out
    {
        dim3 grid((2 * S_DIM) / 128, T_LEN / 128);
        gemm_kernel<<<grid, 256>>>(nullptr, w_out, b_out, out, T_LEN, 2 * S_DIM, H_DIM, 1);
    }
}

// round 16
// speedup vs baseline: 1.0468x; 1.0468x over previous
#include <cuda_runtime.h>
#include <math.h>

// Problem constants
#define T_LEN 32768
#define D_IN  512
#define H_DIM 1024
#define S_DIM 256
#define G3    (3 * H_DIM)   // 3072

// Scan configuration: 128 persistent CTAs, 8 h-outputs per CTA, 24 w_hh rows per CTA.
#define NC           128
#define JPC          (H_DIM / NC)        // 8
#define SCAN_THREADS 256                 // 8 warps, 3 rows per warp

typedef unsigned long long u64;

// Fused publication record: 8 h-values + step tag in ONE 128B line.
// Producer: st.cg data, __syncthreads, st.release.gpu tag (orders data<tag).
// Consumer: ld.acquire.gpu poll tag, then ld.cg data from the same line.
// 128B alignment -> each record owns its L2 line (contention spread 128-way).
struct __align__(128) Rec {
    float    h[8];        // 32B
    unsigned tag;         // step+1 of the h stored here
    unsigned pad[23];     // pad to 128B
};

// -------- Scratch (device globals; no dynamic allocation allowed) ----------
__device__ float g_igates[(size_t)T_LEN * G3];   // ~403 MB
__device__ float g_hs[(size_t)T_LEN * H_DIM];    // ~134 MB
__device__ Rec   g_rec[2][NC];                   // ping-pong fused records, 32KB

// ---------------------------------------------------------------------------
// Init: records[0] = chunks of tanh(h0) with tag=1; records[1] tag=0.
// Runs every replay (graph-capture safe, stream-ordered before scan).
// ---------------------------------------------------------------------------
__global__ void init_kernel(const float* __restrict__ h0)
{
    int i = threadIdx.x;                  // 0..1023
    if (i < H_DIM)
        g_rec[0][i >> 3].h[i & 7] = tanhf(h0[i]);
    if (i < NC) {
        g_rec[0][i].tag = 1u;
        g_rec[1][i].tag = 0u;
    }
}

// ---------------------------------------------------------------------------
// Tiled fp32 GEMM:  C[m][n] = sum_k A[m][k] * B[n][k] + bias[n]
//   mode 0: A = param (y),  C = g_igates                        (igates GEMM)
//   mode 1: A = g_hs,       C = d_out split + softplus epilogue (output GEMM)
// 128x128x16 tiles, 256 threads, conflict-free float4 fragments.
// ---------------------------------------------------------------------------
__global__ __launch_bounds__(256) void gemm_kernel(
    const float* __restrict__ Ain,
    const float* __restrict__ Bm,
    const float* __restrict__ bias,
    float* __restrict__ Cout,
    int M, int N, int K, int mode)
{
    __shared__ float As[16][128];
    __shared__ float Bs[16][128];

    const float* A = (mode == 0) ? Ain : g_hs;

    int bm = blockIdx.y;
    int bn = blockIdx.x;
    int tid  = threadIdx.x;
    int warp = tid >> 5;
    int lane = tid & 31;
    int wy = warp >> 1;
    int wx = warp & 1;
    int r  = lane >> 3;
    int c  = lane & 7;

    const float* Ab = A  + (size_t)bm * 128 * K;
    const float* Bb = Bm + (size_t)bn * 128 * K;

    float acc[2][4][2][4];
#pragma unroll
    for (int ia = 0; ia < 2; ia++)
#pragma unroll
        for (int i = 0; i < 4; i++)
#pragma unroll
            for (int jb = 0; jb < 2; jb++)
#pragma unroll
                for (int j = 0; j < 4; j++) acc[ia][i][jb][j] = 0.f;

    for (int kt = 0; kt < K; kt += 16) {
#pragma unroll
        for (int s = 0; s < 2; s++) {
            int idx = tid * 2 + s;
            int row = idx >> 2;
            int k4  = idx & 3;
            float4 va = *(const float4*)(Ab + (size_t)row * K + kt + k4 * 4);
            As[k4 * 4 + 0][row] = va.x;
            As[k4 * 4 + 1][row] = va.y;
            As[k4 * 4 + 2][row] = va.z;
            As[k4 * 4 + 3][row] = va.w;
            float4 vb = *(const float4*)(Bb + (size_t)row * K + kt + k4 * 4);
            Bs[k4 * 4 + 0][row] = vb.x;
            Bs[k4 * 4 + 1][row] = vb.y;
            Bs[k4 * 4 + 2][row] = vb.z;
            Bs[k4 * 4 + 3][row] = vb.w;
        }
        __syncthreads();

#pragma unroll
        for (int kk = 0; kk < 16; kk++) {
            float4 a0 = *(const float4*)&As[kk][wy * 32 + r * 4];
            float4 a1 = *(const float4*)&As[kk][wy * 32 + r * 4 + 16];
            float4 b0 = *(const float4*)&Bs[kk][wx * 64 + c * 4];
            float4 b1 = *(const float4*)&Bs[kk][wx * 64 + c * 4 + 32];
            float av[2][4] = {{a0.x, a0.y, a0.z, a0.w}, {a1.x, a1.y, a1.z, a1.w}};
            float bv[2][4] = {{b0.x, b0.y, b0.z, b0.w}, {b1.x, b1.y, b1.z, b1.w}};
#pragma unroll
            for (int ia = 0; ia < 2; ia++)
#pragma unroll
                for (int i = 0; i < 4; i++)
#pragma unroll
                    for (int jb = 0; jb < 2; jb++)
#pragma unroll
                        for (int j = 0; j < 4; j++)
                            acc[ia][i][jb][j] += av[ia][i] * bv[jb][j];
        }
        __syncthreads();
    }

#pragma unroll
    for (int ia = 0; ia < 2; ia++) {
#pragma unroll
        for (int i = 0; i < 4; i++) {
            int m = bm * 128 + wy * 32 + r * 4 + ia * 16 + i;
#pragma unroll
            for (int jb = 0; jb < 2; jb++) {
#pragma unroll
                for (int j = 0; j < 4; j++) {
                    int n = bn * 128 + wx * 64 + c * 4 + jb * 32 + j;
                    float v = acc[ia][i][jb][j] + bias[n];
                    if (mode == 0) {
                        g_igates[(size_t)m * G3 + n] = v;
                    } else {
                        if (n < S_DIM) {
                            Cout[(size_t)m * S_DIM + n] = v;             // nat1
                        } else {
                            float sp = fmaxf(v, 0.f) + log1pf(expf(-fabsf(v)));
                            Cout[(size_t)T_LEN * S_DIM + (size_t)m * S_DIM + (n - S_DIM)] = sp;
                        }
                    }
                }
            }
        }
    }
}

// ---------------------------------------------------------------------------
// Persistent GRU scan with FUSED publication records.
//   Step t: buffer b=t&1 holds h_t (tag t+1).
//   Consumers (warps 0-3, lane L handles record r=warp*32+L):
//     poll rec[b][r].tag (ld.acquire.gpu) until >= t+1, then ld.cg the 32B of
//     h data from the SAME line and STS into the staging smem.
//   Producers (tid<8): st.cg h' into rec[b^1][c].h[tid]; sync; tid0 releases
//     tag=t+2. g_hs store after the release (off critical path).
//   WAR safety across the 1-step skew: a CTA can overwrite rec[b][c] (for step
//   t+2) only after observing ALL tags>=t+2, which requires every consumer's
//   step-t reads of rec[b] to have completed (reads precede that CTA's own
//   release of t+2 in program order). Transitively ordered -> no torn reads.
//   ig prefetch is double-buffered one step ahead (hides DRAM+TLB latency).
// ---------------------------------------------------------------------------
__global__ __launch_bounds__(SCAN_THREADS, 1) void scan_kernel(
    const float* __restrict__ w_hh,
    const float* __restrict__ bn_vec)
{
    int c    = blockIdx.x;
    int tid  = threadIdx.x;
    int warp = tid >> 5;
    int lane = tid & 31;

    // --- Weight slice in registers as f32x2 pairs -----------------------
    ulonglong2 w[3][8];
#pragma unroll
    for (int rr = 0; rr < 3; rr++) {
        int lr   = warp * 3 + rr;
        int grow = (lr >> 3) * H_DIM + c * JPC + (lr & 7);
        const float* wr = w_hh + (size_t)grow * H_DIM;
#pragma unroll
        for (int i = 0; i < 8; i++)
            w[rr][i] = *(const ulonglong2*)(wr + i * 128 + lane * 4);
    }

    float bnv = (tid < JPC) ? bn_vec[c * JPC + tid] : 0.f;

    __shared__ float4 hsm4[H_DIM / 4];   // staged h, 4KB
    __shared__ float  red[24];
    __shared__ float  igs[24];

    int rrec = warp * 32 + lane;         // record this lane polls (warps 0-3)

    // ig double-buffer: load step-0 gates up front.
    float ig_cur = 0.f, ig_nxt = 0.f;
    int g_gate = tid >> 3, g_joff = tid & 7;
    if (tid < 24)
        ig_cur = __ldcg(&g_igates[(size_t)0 * G3 + g_gate * H_DIM + c * JPC + g_joff]);

    for (int t = 0; t < T_LEN; t++) {
        // 1) Prefetch NEXT step's input gates (full step of latency cover).
        if (tid < 24 && t + 1 < T_LEN)
            ig_nxt = __ldcg(&g_igates[(size_t)(t + 1) * G3 + g_gate * H_DIM + c * JPC + g_joff]);

        // 2) Fused wait+fetch: poll tag, then read h data from the same line.
        if (warp < 4) {
            Rec* rp = &g_rec[t & 1][rrec];
            unsigned v;
            do {
                asm volatile("ld.global.acquire.gpu.u32 %0, [%1];"
                             : "=r"(v) : "l"(&rp->tag));
            } while (v < (unsigned)(t + 1));
            float4 d0 = __ldcg((const float4*)&rp->h[0]);
            float4 d1 = __ldcg((const float4*)&rp->h[4]);
            hsm4[rrec * 2 + 0] = d0;
            hsm4[rrec * 2 + 1] = d1;
        }
        __syncthreads();

        float hprev = (tid < JPC) ? ((const float*)hsm4)[c * JPC + tid] : 0.f;

        // 3) 3 dot-products of length 1024 per warp via packed f32x2 FMA.
        u64 a0l = 0, a0h = 0, a1l = 0, a1h = 0, a2l = 0, a2h = 0;
#pragma unroll
        for (int i = 0; i < 8; i++) {
            ulonglong2 h2 = *(const ulonglong2*)&hsm4[i * 32 + lane];
            asm volatile("fma.rn.f32x2 %0, %1, %2, %0;" : "+l"(a0l) : "l"(w[0][i].x), "l"(h2.x));
            asm volatile("fma.rn.f32x2 %0, %1, %2, %0;" : "+l"(a0h) : "l"(w[0][i].y), "l"(h2.y));
            asm volatile("fma.rn.f32x2 %0, %1, %2, %0;" : "+l"(a1l) : "l"(w[1][i].x), "l"(h2.x));
            asm volatile("fma.rn.f32x2 %0, %1, %2, %0;" : "+l"(a1h) : "l"(w[1][i].y), "l"(h2.y));
            asm volatile("fma.rn.f32x2 %0, %1, %2, %0;" : "+l"(a2l) : "l"(w[2][i].x), "l"(h2.x));
            asm volatile("fma.rn.f32x2 %0, %1, %2, %0;" : "+l"(a2h) : "l"(w[2][i].y), "l"(h2.y));
        }
        float acc0 = __uint_as_float((unsigned)a0l) + __uint_as_float((unsigned)(a0l >> 32))
                   + __uint_as_float((unsigned)a0h) + __uint_as_float((unsigned)(a0h >> 32));
        float acc1 = __uint_as_float((unsigned)a1l) + __uint_as_float((unsigned)(a1l >> 32))
                   + __uint_as_float((unsigned)a1h) + __uint_as_float((unsigned)(a1h >> 32));
        float acc2 = __uint_as_float((unsigned)a2l) + __uint_as_float((unsigned)(a2l >> 32))
                   + __uint_as_float((unsigned)a2h) + __uint_as_float((unsigned)(a2h >> 32));
#pragma unroll
        for (int off = 16; off > 0; off >>= 1) {
            acc0 += __shfl_xor_sync(0xffffffffu, acc0, off);
            acc1 += __shfl_xor_sync(0xffffffffu, acc1, off);
            acc2 += __shfl_xor_sync(0xffffffffu, acc2, off);
        }
        if (lane == 0) {
            red[warp * 3 + 0] = acc0;
            red[warp * 3 + 1] = acc1;
            red[warp * 3 + 2] = acc2;
        }
        if (tid < 24) igs[tid] = ig_cur;
        __syncthreads();

        // 4) Gate math; publish h' data into the NEXT buffer's record.
        float hnew = 0.f;
        if (tid < JPC) {
            float hrv = red[tid], hzv = red[8 + tid], hnv = red[16 + tid];
            float irv = igs[tid], izv = igs[8 + tid], innv = igs[16 + tid];
            float r = 1.f / (1.f + expf(-(irv + hrv)));
            float z = 1.f / (1.f + expf(-(izv + hzv)));
            float n = tanhf(innv + r * (hnv + bnv));
            hnew = n + z * (hprev - n);
            asm volatile("st.global.cg.f32 [%0], %1;"
                         :: "l"(&g_rec[(t + 1) & 1][c].h[tid]), "f"(hnew));
        }
        __syncthreads();   // all 8 data stores issued before the tag release

        if (tid == 0) {
            asm volatile("st.global.release.gpu.u32 [%0], %1;"
                         :: "l"(&g_rec[(t + 1) & 1][c].tag), "r"((unsigned)(t + 2)));
        }

        // g_hs store off the critical path (after tag publication).
        if (tid < JPC)
            g_hs[(size_t)t * H_DIM + c * JPC + tid] = hnew;

        ig_cur = ig_nxt;
    }
}

// ---------------------------------------------------------------------------
extern "C" void kernel_launch(void* const* d_in, const int* in_sizes, int n_in,
                              void* d_out, int out_size)
{
    const float* y     = (const float*)d_in[0];  // [T, D]
    const float* h0    = (const float*)d_in[1];  // [H]
    const float* w_ih  = (const float*)d_in[2];  // [3H, D]
    const float* w_hh  = (const float*)d_in[3];  // [3H, H]
    const float* b     = (const float*)d_in[4];  // [3H]
    const float* bn    = (const float*)d_in[5];  // [H]
    const float* w_out = (const float*)d_in[6];  // [2S, H]
    const float* b_out = (const float*)d_in[7];  // [2S]
    float* out = (float*)d_out;                  // [T*S nat1][T*S softplus(nat2)]

    // 1) init records
    init_kernel<<<1, 1024>>>(h0);

    // 2) igates = y @ w_ih.T + b   -> g_igates  [T, 3H]
    {
        dim3 grid(G3 / 128, T_LEN / 128);
        gemm_kernel<<<grid, 256>>>(y, w_ih, b, nullptr, T_LEN, G3, D_IN, 0);
    }

    // 3) sequential GRU scan -> g_hs [T, H]
    scan_kernel<<<NC, SCAN_THREADS>>>(w_hh, bn);

    // 4) out = hs @ w_out.T + b_out; split + softplus -> d_out
    {
        dim3 grid((2 * S_DIM) / 128, T_LEN / 128);
        gemm_kernel<<<grid, 256>>>(nullptr, w_out, b_out, out, T_LEN, 2 * S_DIM, H_DIM, 1);
    }
}